// round 12
// baseline (speedup 1.0000x reference)
#include <cuda_runtime.h>
#include <cstdint>

// ---------------------------------------------------------------------------
// Problem constants
// ---------------------------------------------------------------------------
#define EDIM   1024
#define NAQ    128
#define BSZ    256
#define NROWS  (BSZ * NAQ)          // 32768
#define QKVDIM 3072
#define HEADS  16
#define HDIM   64
#define NBH    (BSZ * HEADS)        // 4096 attention batches
#define OUT_ELEMS (NROWS * EDIM)
#define NTILES 3072                 // 256 bm x 12 bn
#define NSM    148

// ---------------------------------------------------------------------------
// Scratch (device globals: allocation-free)
// ---------------------------------------------------------------------------
__device__ float g_xn  [(size_t)NROWS * EDIM];       // ln1(x), tf32-rounded
__device__ float g_qkv [(size_t)NROWS * QKVDIM];     // qkv (q scaled), tf32-rounded
__device__ float g_attn[(size_t)NROWS * EDIM];       // attention output
__device__ float g_wtf [(size_t)QKVDIM * EDIM];      // in_w, fragment-permuted tf32

// ---------------------------------------------------------------------------
// Helpers (portable subset: harness lowers through compute_103)
// ---------------------------------------------------------------------------
__device__ __forceinline__ uint32_t smem_u32(const void* p) {
    uint32_t a;
    asm("{ .reg .u64 t; cvta.to.shared.u64 t, %1; cvt.u32.u64 %0, t; }"
        : "=r"(a) : "l"(p));
    return a;
}
__device__ __forceinline__ void cp_async16(uint32_t dst, const void* src) {
    asm volatile("cp.async.cg.shared.global [%0], [%1], 16;"
                 :: "r"(dst), "l"(src) : "memory");
}
#define CP_COMMIT() asm volatile("cp.async.commit_group;" ::: "memory")

__device__ __forceinline__ uint32_t f2tf(float f) {
    uint32_t r;
    asm("cvt.rna.tf32.f32 %0, %1;" : "=r"(r) : "f"(f));
    return r;
}
__device__ __forceinline__ float roundtf(float f) {
    return __uint_as_float(f2tf(f));
}
__device__ __forceinline__ void mma_tf32(float* c, const uint32_t* a,
                                         uint32_t b0, uint32_t b1) {
    asm volatile(
        "mma.sync.aligned.m16n8k8.row.col.f32.tf32.tf32.f32 "
        "{%0,%1,%2,%3}, {%4,%5,%6,%7}, {%8,%9}, {%0,%1,%2,%3};"
        : "+f"(c[0]), "+f"(c[1]), "+f"(c[2]), "+f"(c[3])
        : "r"(a[0]), "r"(a[1]), "r"(a[2]), "r"(a[3]), "r"(b0), "r"(b1));
}
__device__ __forceinline__ void ldsm4(uint32_t* r, uint32_t addr) {
    asm volatile("ldmatrix.sync.aligned.m8n8.x4.shared.b16 {%0,%1,%2,%3}, [%4];"
                 : "=r"(r[0]), "=r"(r[1]), "=r"(r[2]), "=r"(r[3]) : "r"(addr));
}

// ---------------------------------------------------------------------------
// LayerNorm (+ optional residual, optional tf32 rounding of output)
// ---------------------------------------------------------------------------
__global__ __launch_bounds__(256) void ln_kernel(
    const float* __restrict__ in, const float* __restrict__ res,
    const float* __restrict__ w, const float* __restrict__ b,
    float* __restrict__ out, int rnd)
{
    __shared__ float red_s[8];
    __shared__ float red_q[8];
    size_t row = blockIdx.x;
    int t = threadIdx.x;

    const float4* px = (const float4*)(in + row * EDIM);
    float4 v = px[t];
    if (res != nullptr) {
        const float4* pr = (const float4*)(res + row * EDIM);
        float4 rv = pr[t];
        v.x += rv.x; v.y += rv.y; v.z += rv.z; v.w += rv.w;
    }
    float s = v.x + v.y + v.z + v.w;
    float q = v.x * v.x + v.y * v.y + v.z * v.z + v.w * v.w;
#pragma unroll
    for (int o = 16; o > 0; o >>= 1) {
        s += __shfl_xor_sync(0xffffffffu, s, o);
        q += __shfl_xor_sync(0xffffffffu, q, o);
    }
    if ((t & 31) == 0) { red_s[t >> 5] = s; red_q[t >> 5] = q; }
    __syncthreads();
    float tot = 0.f, totq = 0.f;
#pragma unroll
    for (int k = 0; k < 8; ++k) { tot += red_s[k]; totq += red_q[k]; }

    float mean = tot * (1.0f / EDIM);
    float var  = totq * (1.0f / EDIM) - mean * mean;
    float rstd = rsqrtf(var + 1e-5f);

    int c0 = t * 4;
    float4 wv = *(const float4*)(w + c0);
    float4 bv = *(const float4*)(b + c0);
    float4 o4;
    o4.x = (v.x - mean) * rstd * wv.x + bv.x;
    o4.y = (v.y - mean) * rstd * wv.y + bv.y;
    o4.z = (v.z - mean) * rstd * wv.z + bv.z;
    o4.w = (v.w - mean) * rstd * wv.w + bv.w;
    if (rnd) {
        o4.x = roundtf(o4.x); o4.y = roundtf(o4.y);
        o4.z = roundtf(o4.z); o4.w = roundtf(o4.w);
    }
    ((float4*)(out + row * EDIM))[t] = o4;
}

// ---------------------------------------------------------------------------
// Weight permute: in_w (3072x1024 row-major fp32) -> B-fragment order, tf32.
// Output: [nb 0..383][kb 0..127][lane 0..31][2]
//   val = { W[8nb+fr][8kb+fc], W[8nb+fr][8kb+fc+4] },  fr=lane>>2, fc=lane&3
// ---------------------------------------------------------------------------
#define PW_SMEM (16 * 1028 * 4)     // 65792 bytes

__global__ __launch_bounds__(256) void permute_w_kernel(
    const float* __restrict__ w, float* __restrict__ wp)
{
    extern __shared__ float s[];
    int blk = blockIdx.x;           // 0..191
    int t = threadIdx.x;
#pragma unroll
    for (int rr = 0; rr < 16; ++rr) {
        float4 v = *(const float4*)(w + (size_t)(blk * 16 + rr) * EDIM + t * 4);
        *(float4*)&s[rr * 1028 + t * 4] = v;
    }
    __syncthreads();
#pragma unroll
    for (int it = 0; it < 32; ++it) {
        int o2 = t + it * 256;              // 0..8191
        int nb_l = o2 >> 12;                // 0..1
        int kb   = (o2 >> 5) & 127;
        int lane = o2 & 31;
        int fr = lane >> 2, fc = lane & 3;
        int rl = nb_l * 8 + fr;
        float2 o;
        o.x = roundtf(s[rl * 1028 + kb * 8 + fc]);
        o.y = roundtf(s[rl * 1028 + kb * 8 + fc + 4]);
        *(float2*)(wp + (((size_t)(blk * 2 + nb_l) * 128 + kb) * 32 + lane) * 2) = o;
    }
}

// ---------------------------------------------------------------------------
// Persistent TF32 QKV GEMM. 148 CTAs; tile = bid + k*148 with
//   bn = tile % 12, bm = tile / 12  -> concurrent window = ~13 bm blocks
//   (6.5MB A) + all W (12MB): whole working set L2-resident.
// BK=64 chunks, 2-stage pipeline (100KB/stage). 8 warps (2x4), warp tile
// 64x64, LDSM A-fragments (row stride 272B conflict-free), permuted-W LDS.64.
// ---------------------------------------------------------------------------
#define GS_A_BYTES 34816                     // 128 rows x 272B
#define GS_B_BYTES 65536                     // 32 nb x 8 kb x 256B
#define GS_STAGE   (GS_A_BYTES + GS_B_BYTES) // 100352
#define GS_SMEM    (2 * GS_STAGE)            // 200704

__global__ __launch_bounds__(256, 1) void qkv_gemm_tf32_kernel(
    const float* __restrict__ A, const float* __restrict__ Wp,
    const float* __restrict__ bias, float* __restrict__ C)
{
    extern __shared__ char smem[];
    uint32_t sb = smem_u32(smem);
    int tid  = threadIdx.x;
    int lane = tid & 31;
    int wid  = tid >> 5;          // 0..7
    int wm   = wid >> 2;          // 0..1
    int wn   = wid & 3;           // 0..3
    int bid  = blockIdx.x;        // 0..147

    int nt_local = (NTILES - bid + NSM - 1) / NSM;
    int total_chunks = nt_local * 16;        // 16 chunks of k64 per tile

    auto load_chunk = [&](int q) {
        int tile = bid + (q >> 4) * NSM;
        int c    = q & 15;
        int bn = tile % 12;
        int bm = tile / 12;
        uint32_t base = sb + (q & 1) * GS_STAGE;
        int kbase = c * 64;
#pragma unroll
        for (int i = 0; i < 8; ++i) {      // A: 2048 granules (128 x 64f)
            int g = tid + i * 256;
            int r = g >> 4, kk = g & 15;
            cp_async16(base + r * 272 + kk * 16,
                       A + (size_t)(bm * 128 + r) * EDIM + kbase + kk * 4);
        }
#pragma unroll
        for (int i = 0; i < 16; ++i) {     // W: 4096 granules (permuted blocks)
            int g = tid + i * 256;
            int nb = g >> 7, kb = (g >> 4) & 7, pr = g & 15;
            cp_async16(base + GS_A_BYTES + g * 16,
                       Wp + ((size_t)(bn * 32 + nb) * 128 + c * 8 + kb) * 64 + pr * 4);
        }
    };

    load_chunk(0); CP_COMMIT();
    load_chunk(1); CP_COMMIT();

    float acc[4][8][4];
#pragma unroll
    for (int i = 0; i < 4; ++i)
#pragma unroll
        for (int j = 0; j < 8; ++j)
#pragma unroll
            for (int k = 0; k < 4; ++k) acc[i][j][k] = 0.f;

    uint32_t a_off = (uint32_t)((wm * 64 + (lane & 15)) * 272 + (lane >> 4) * 16);
    int qr = lane >> 2;
    int tc = (lane & 3) * 2;

    for (int q = 0; q < total_chunks; ++q) {
        asm volatile("cp.async.wait_group 1;" ::: "memory");
        __syncthreads();
        int s = q & 1;
        uint32_t sA = sb + s * GS_STAGE;
        const char* Bp = smem + s * GS_STAGE + GS_A_BYTES;

#pragma unroll
        for (int ks = 0; ks < 64; ks += 8) {
            int kb = ks >> 3;
            uint32_t fa[4][4];
            uint2 fb[8];
#pragma unroll
            for (int mt = 0; mt < 4; ++mt)
                ldsm4(fa[mt], sA + a_off + mt * (16 * 272) + ks * 4);
#pragma unroll
            for (int nt = 0; nt < 8; ++nt) {
                int nbl = wn * 8 + nt;
                fb[nt] = *(const uint2*)(Bp + (nbl * 8 + kb) * 256 + lane * 8);
            }
#pragma unroll
            for (int mt = 0; mt < 4; ++mt)
#pragma unroll
                for (int nt = 0; nt < 8; ++nt)
                    mma_tf32(acc[mt][nt], fa[mt], fb[nt].x, fb[nt].y);
        }

        if ((q & 15) == 15) {
            // ---- epilogue for this tile (next-tile chunk already in flight) ----
            int tile = bid + (q >> 4) * NSM;
            int bn = tile % 12;
            int bm = tile / 12;
            float scale = (bn < 4) ? 0.125f : 1.0f;   // q * HD^-0.5
#pragma unroll
            for (int mt = 0; mt < 4; ++mt) {
#pragma unroll
                for (int nt = 0; nt < 8; ++nt) {
                    int row = bm * 128 + wm * 64 + mt * 16 + qr;
                    int col = bn * 256 + wn * 64 + nt * 8 + tc;
                    float b0 = bias[col], b1 = bias[col + 1];
                    float2 o0 = make_float2(roundtf((acc[mt][nt][0] + b0) * scale),
                                            roundtf((acc[mt][nt][1] + b1) * scale));
                    float2 o1 = make_float2(roundtf((acc[mt][nt][2] + b0) * scale),
                                            roundtf((acc[mt][nt][3] + b1) * scale));
                    *(float2*)(C + (size_t)row * QKVDIM + col)       = o0;
                    *(float2*)(C + (size_t)(row + 8) * QKVDIM + col) = o1;
#pragma unroll
                    for (int k = 0; k < 4; ++k) acc[mt][nt][k] = 0.f;
                }
            }
        }

        __syncthreads();   // all warps done with slot s before reloading it
        if (q + 2 < total_chunks) load_chunk(q + 2);
        CP_COMMIT();
    }
}

// ---------------------------------------------------------------------------
// Attention via TF32 mma.sync + LDSM: one block (256 thr) per bh; 2 CTAs/SM.
// SMEM (floats): Qs 128x68 @0, Ks 128x68 @8704, Vs 128x72 @17408,
//   AVG partials 8x128 @26624.  S (128x132) overlays Qs+Ks after QK^T.
// avg_w fused into softmax (register column partials per warp).
// ---------------------------------------------------------------------------
#define AT_K_F   8704
#define AT_V_F   17408
#define AT_AVG_F 26624
#define ATTN_SMEM_BYTES ((AT_AVG_F + 8 * 128) * 4)   // 110592

__global__ void __launch_bounds__(256, 2) attn_kernel(
    const float* __restrict__ qkv, float* __restrict__ attn,
    float* __restrict__ avg_out)
{
    extern __shared__ float sm[];
    float* Vs  = sm + AT_V_F;
    float* AVG = sm + AT_AVG_F;
    float* S   = sm;                // overlays Qs+Ks after QK phase
    uint32_t sbase = smem_u32(sm);

    int bh  = blockIdx.x;
    int p   = bh >> 11;
    int rr  = bh & 2047;
    int nid = rr >> 4;
    int h   = rr & 15;
    int t   = threadIdx.x;
    int lane = t & 31;
    int wid  = t >> 5;            // 0..7
    int wm   = wid >> 2;          // 0..1
    int wn   = wid & 3;           // 0..3
    int col = h * HDIM;

    // ---- async gather of Q,K (group 1) and V (group 0, overlapped) ----
#pragma unroll
    for (int it = 0; it < 8; ++it) {
        int f  = t + it * 256;          // 0..2047
        int i  = f >> 4;                // row 0..127
        int d0 = (f & 15) << 2;         // 0..60
        int rowoff = ((2 * i + p) * 128 + nid) * QKVDIM;
        cp_async16(sbase + (i * 68 + d0) * 4,
                   qkv + rowoff + col + d0);
        cp_async16(sbase + (AT_K_F + i * 68 + d0) * 4,
                   qkv + rowoff + 1024 + col + d0);
    }
    CP_COMMIT();
#pragma unroll
    for (int it = 0; it < 8; ++it) {
        int f  = t + it * 256;
        int i  = f >> 4;
        int d0 = (f & 15) << 2;
        int rowoff = ((2 * i + p) * 128 + nid) * QKVDIM;
        cp_async16(sbase + (AT_V_F + i * 72 + d0) * 4,
                   qkv + rowoff + 2048 + col + d0);
    }
    CP_COMMIT();
    asm volatile("cp.async.wait_group 1;" ::: "memory");  // Q,K ready
    __syncthreads();

    // LDSM per-lane offsets (bytes)
    uint32_t aq_off = (uint32_t)((wm * 64 + (lane & 15)) * 272 + (lane >> 4) * 16);
    uint32_t bk_row = (uint32_t)(wn * 32 + (lane & 7) + ((lane & 16) >> 1));
    uint32_t bk_off = AT_K_F * 4 + bk_row * 272 + (((lane >> 3) & 1) * 16);

    // ---- scores = Q K^T (TF32), warp tile 64x32, K=64; kept in registers ----
    float acc[4][4][4];
#pragma unroll
    for (int i = 0; i < 4; ++i)
#pragma unroll
        for (int j = 0; j < 4; ++j)
#pragma unroll
            for (int k = 0; k < 4; ++k) acc[i][j][k] = 0.f;

#pragma unroll
    for (int ks = 0; ks < 64; ks += 8) {
        uint32_t fa[4][4], fbp[2][4];
#pragma unroll
        for (int mt = 0; mt < 4; ++mt)
            ldsm4(fa[mt], sbase + aq_off + mt * (16 * 272) + ks * 4);
#pragma unroll
        for (int ntp = 0; ntp < 2; ++ntp)
            ldsm4(fbp[ntp], sbase + bk_off + ntp * (16 * 272) + ks * 4);
#pragma unroll
        for (int mt = 0; mt < 4; ++mt) {
#pragma unroll
            for (int nt = 0; nt < 4; ++nt) {
                int np = nt >> 1, hh = (nt & 1) * 2;
                mma_tf32(acc[mt][nt], fa[mt], fbp[np][hh], fbp[np][hh + 1]);
            }
        }
    }
    __syncthreads();   // all warps done reading Qs/Ks before S overlays them

    {
        int qr = lane >> 2, tc = (lane & 3) * 2;
#pragma unroll
        for (int mt = 0; mt < 4; ++mt) {
#pragma unroll
            for (int nt = 0; nt < 4; ++nt) {
                int row = wm * 64 + mt * 16 + qr;
                int cc  = wn * 32 + nt * 8 + tc;
                S[row * 132 + cc]           = acc[mt][nt][0];
                S[row * 132 + cc + 1]       = acc[mt][nt][1];
                S[(row + 8) * 132 + cc]     = acc[mt][nt][2];
                S[(row + 8) * 132 + cc + 1] = acc[mt][nt][3];
            }
        }
    }
    __syncthreads();

    // ---- softmax (16 rows/warp, lane-parallel) + fused avg_w partials ----
    {
        float cs0 = 0.f, cs1 = 0.f, cs2 = 0.f, cs3 = 0.f;
#pragma unroll
        for (int r8 = 0; r8 < 16; ++r8) {
            int row = wid * 16 + r8;
            float4 v = *(float4*)&S[row * 132 + lane * 4];
            float mx = fmaxf(fmaxf(v.x, v.y), fmaxf(v.z, v.w));
#pragma unroll
            for (int o = 16; o > 0; o >>= 1)
                mx = fmaxf(mx, __shfl_xor_sync(0xffffffffu, mx, o));
            v.x = __expf(v.x - mx); v.y = __expf(v.y - mx);
            v.z = __expf(v.z - mx); v.w = __expf(v.w - mx);
            float sum = v.x + v.y + v.z + v.w;
#pragma unroll
            for (int o = 16; o > 0; o >>= 1)
                sum += __shfl_xor_sync(0xffffffffu, sum, o);
            float inv = 1.0f / sum;
            v.x = roundtf(v.x * inv); v.y = roundtf(v.y * inv);
            v.z = roundtf(v.z * inv); v.w = roundtf(v.w * inv);
            cs0 += v.x; cs1 += v.y; cs2 += v.z; cs3 += v.w;
            *(float4*)&S[row * 132 + lane * 4] = v;
        }
        *(float4*)&AVG[wid * 128 + lane * 4] = make_float4(cs0, cs1, cs2, cs3);
    }
    asm volatile("cp.async.wait_group 0;" ::: "memory");  // V ready
    __syncthreads();

    // ---- avg_w final reduce across 8 warps ----
    if (t < 128) {
        float s = 0.f;
#pragma unroll
        for (int w = 0; w < 8; ++w) s += AVG[w * 128 + t];
        avg_out[bh * 128 + t] = s * 0.0625f;
    }

    // ---- A·V (TF32): A = S via LDSM, warp tile 64x16, K=128 ----
    float av[4][2][4];
    {
        int fr = lane >> 2;
        int fc = lane & 3;
        uint32_t as_off = (uint32_t)((wm * 64 + (lane & 15)) * 528 + (lane >> 4) * 16);
#pragma unroll
        for (int i = 0; i < 4; ++i)
#pragma unroll
            for (int j = 0; j < 2; ++j)
#pragma unroll
                for (int k = 0; k < 4; ++k) av[i][j][k] = 0.f;

#pragma unroll
        for (int ks = 0; ks < 128; ks += 8) {
            uint32_t fa[4][4], fb[2][2];
#pragma unroll
            for (int mt = 0; mt < 4; ++mt)
                ldsm4(fa[mt], sbase + as_off + mt * (16 * 528) + ks * 4);
#pragma unroll
            for (int nt = 0; nt < 2; ++nt) {
                int nb = wn * 16 + nt * 8 + fr;
                fb[nt][0] = __float_as_uint(Vs[(ks + fc) * 72 + nb]);
                fb[nt][1] = __float_as_uint(Vs[(ks + fc + 4) * 72 + nb]);
            }
#pragma unroll
            for (int mt = 0; mt < 4; ++mt)
#pragma unroll
                for (int nt = 0; nt < 2; ++nt)
                    mma_tf32(av[mt][nt], fa[mt], fb[nt][0], fb[nt][1]);
        }
    }
    __syncthreads();   // everyone done reading S before OUT overlays it

    // ---- stage output in smem (stride 68), then coalesced global stores ----
    {
        int qr = lane >> 2, tc = (lane & 3) * 2;
#pragma unroll
        for (int mt = 0; mt < 4; ++mt) {
#pragma unroll
            for (int nt = 0; nt < 2; ++nt) {
                int row = wm * 64 + mt * 16 + qr;
                int cc  = wn * 16 + nt * 8 + tc;
                *(float2*)&S[row * 68 + cc] =
                    make_float2(av[mt][nt][0], av[mt][nt][1]);
                *(float2*)&S[(row + 8) * 68 + cc] =
                    make_float2(av[mt][nt][2], av[mt][nt][3]);
            }
        }
    }
    __syncthreads();
#pragma unroll
    for (int it = 0; it < 8; ++it) {
        int f  = t + it * 256;
        int row = f >> 4;
        int c4  = (f & 15) << 2;
        float4 v = *(float4*)&S[row * 68 + c4];
        int orow = (2 * row + p) * 128 + nid;
        *(float4*)&attn[(size_t)orow * EDIM + col + c4] = v;
    }
}

// ---------------------------------------------------------------------------
// Launch
// ---------------------------------------------------------------------------
extern "C" void kernel_launch(void* const* d_in, const int* in_sizes, int n_in,
                              void* d_out, int out_size)
{
    const float* x    = (const float*)d_in[0];
    const float* ln1w = (const float*)d_in[1];
    const float* ln1b = (const float*)d_in[2];
    const float* inw  = (const float*)d_in[3];
    const float* inb  = (const float*)d_in[4];
    const float* ln2w = (const float*)d_in[5];
    const float* ln2b = (const float*)d_in[6];
    float* out = (float*)d_out;

    float *xn, *qkv, *attn, *wtf;
    cudaGetSymbolAddress((void**)&xn,   g_xn);
    cudaGetSymbolAddress((void**)&qkv,  g_qkv);
    cudaGetSymbolAddress((void**)&attn, g_attn);
    cudaGetSymbolAddress((void**)&wtf,  g_wtf);

    cudaFuncSetAttribute(attn_kernel,
                         cudaFuncAttributeMaxDynamicSharedMemorySize,
                         ATTN_SMEM_BYTES);
    cudaFuncSetAttribute(qkv_gemm_tf32_kernel,
                         cudaFuncAttributeMaxDynamicSharedMemorySize,
                         GS_SMEM);
    cudaFuncSetAttribute(permute_w_kernel,
                         cudaFuncAttributeMaxDynamicSharedMemorySize,
                         PW_SMEM);

    // 1) xn = LN1(x), tf32-rounded (also the residual for LN2)
    ln_kernel<<<NROWS, 256>>>(x, nullptr, ln1w, ln1b, xn, 1);
    // 2) permute + round weights into B-fragment layout
    permute_w_kernel<<<192, 256, PW_SMEM>>>(inw, wtf);
    // 3) persistent TF32 QKV GEMM (L2-resident tile order, BK=64, 2 stages)
    qkv_gemm_tf32_kernel<<<NSM, 256, GS_SMEM>>>(xn, wtf, inb, qkv);
    // 4) TF32 attention + avg_w (2 CTAs/SM, fused avg, coalesced epilogue)
    attn_kernel<<<NBH, 256, ATTN_SMEM_BYTES>>>(qkv, attn, out + OUT_ELEMS);
    // 5) out = LN2(xn + attn)
    ln_kernel<<<NROWS, 256>>>(xn, attn, ln2w, ln2b, out, 0);
}

// round 13
// speedup vs baseline: 1.0012x; 1.0012x over previous
#include <cuda_runtime.h>
#include <cstdint>

// ---------------------------------------------------------------------------
// Problem constants
// ---------------------------------------------------------------------------
#define EDIM   1024
#define NAQ    128
#define BSZ    256
#define NROWS  (BSZ * NAQ)          // 32768
#define QKVDIM 3072
#define HEADS  16
#define HDIM   64
#define NBH    (BSZ * HEADS)        // 4096 attention batches
#define OUT_ELEMS (NROWS * EDIM)
#define NTILES 3072                 // 256 bm x 12 bn
#define NSM    148

// ---------------------------------------------------------------------------
// Scratch (device globals: allocation-free)
// ---------------------------------------------------------------------------
__device__ float g_xn  [(size_t)NROWS * EDIM];       // ln1(x), tf32-rounded
__device__ float g_qkv [(size_t)NROWS * QKVDIM];     // qkv (q scaled), tf32-rounded
__device__ float g_attn[(size_t)NROWS * EDIM];       // attention output
__device__ float g_wtf [(size_t)QKVDIM * EDIM];      // in_w, fragment-permuted tf32

// ---------------------------------------------------------------------------
// Helpers (portable subset: harness lowers through compute_103)
// ---------------------------------------------------------------------------
__device__ __forceinline__ uint32_t smem_u32(const void* p) {
    uint32_t a;
    asm("{ .reg .u64 t; cvta.to.shared.u64 t, %1; cvt.u32.u64 %0, t; }"
        : "=r"(a) : "l"(p));
    return a;
}
__device__ __forceinline__ void cp_async16(uint32_t dst, const void* src) {
    asm volatile("cp.async.cg.shared.global [%0], [%1], 16;"
                 :: "r"(dst), "l"(src) : "memory");
}
#define CP_COMMIT() asm volatile("cp.async.commit_group;" ::: "memory")

__device__ __forceinline__ uint32_t f2tf(float f) {
    uint32_t r;
    asm("cvt.rna.tf32.f32 %0, %1;" : "=r"(r) : "f"(f));
    return r;
}
__device__ __forceinline__ float roundtf(float f) {
    return __uint_as_float(f2tf(f));
}
__device__ __forceinline__ void mma_tf32(float* c, const uint32_t* a,
                                         uint32_t b0, uint32_t b1) {
    asm volatile(
        "mma.sync.aligned.m16n8k8.row.col.f32.tf32.tf32.f32 "
        "{%0,%1,%2,%3}, {%4,%5,%6,%7}, {%8,%9}, {%0,%1,%2,%3};"
        : "+f"(c[0]), "+f"(c[1]), "+f"(c[2]), "+f"(c[3])
        : "r"(a[0]), "r"(a[1]), "r"(a[2]), "r"(a[3]), "r"(b0), "r"(b1));
}
__device__ __forceinline__ void ldsm4(uint32_t* r, uint32_t addr) {
    asm volatile("ldmatrix.sync.aligned.m8n8.x4.shared.b16 {%0,%1,%2,%3}, [%4];"
                 : "=r"(r[0]), "=r"(r[1]), "=r"(r[2]), "=r"(r[3]) : "r"(addr));
}

// ---------------------------------------------------------------------------
// LayerNorm (+ optional residual, optional tf32 rounding of output)
// ---------------------------------------------------------------------------
__global__ __launch_bounds__(256) void ln_kernel(
    const float* __restrict__ in, const float* __restrict__ res,
    const float* __restrict__ w, const float* __restrict__ b,
    float* __restrict__ out, int rnd)
{
    __shared__ float red_s[8];
    __shared__ float red_q[8];
    size_t row = blockIdx.x;
    int t = threadIdx.x;

    const float4* px = (const float4*)(in + row * EDIM);
    float4 v = px[t];
    if (res != nullptr) {
        const float4* pr = (const float4*)(res + row * EDIM);
        float4 rv = pr[t];
        v.x += rv.x; v.y += rv.y; v.z += rv.z; v.w += rv.w;
    }
    float s = v.x + v.y + v.z + v.w;
    float q = v.x * v.x + v.y * v.y + v.z * v.z + v.w * v.w;
#pragma unroll
    for (int o = 16; o > 0; o >>= 1) {
        s += __shfl_xor_sync(0xffffffffu, s, o);
        q += __shfl_xor_sync(0xffffffffu, q, o);
    }
    if ((t & 31) == 0) { red_s[t >> 5] = s; red_q[t >> 5] = q; }
    __syncthreads();
    float tot = 0.f, totq = 0.f;
#pragma unroll
    for (int k = 0; k < 8; ++k) { tot += red_s[k]; totq += red_q[k]; }

    float mean = tot * (1.0f / EDIM);
    float var  = totq * (1.0f / EDIM) - mean * mean;
    float rstd = rsqrtf(var + 1e-5f);

    int c0 = t * 4;
    float4 wv = *(const float4*)(w + c0);
    float4 bv = *(const float4*)(b + c0);
    float4 o4;
    o4.x = (v.x - mean) * rstd * wv.x + bv.x;
    o4.y = (v.y - mean) * rstd * wv.y + bv.y;
    o4.z = (v.z - mean) * rstd * wv.z + bv.z;
    o4.w = (v.w - mean) * rstd * wv.w + bv.w;
    if (rnd) {
        o4.x = roundtf(o4.x); o4.y = roundtf(o4.y);
        o4.z = roundtf(o4.z); o4.w = roundtf(o4.w);
    }
    ((float4*)(out + row * EDIM))[t] = o4;
}

// ---------------------------------------------------------------------------
// Weight permute: in_w (3072x1024 row-major fp32) -> B-fragment order, tf32.
// Output: [nb 0..383][kb 0..127][lane 0..31][2]
//   val = { W[8nb+fr][8kb+fc], W[8nb+fr][8kb+fc+4] },  fr=lane>>2, fc=lane&3
// ---------------------------------------------------------------------------
#define PW_SMEM (16 * 1028 * 4)     // 65792 bytes

__global__ __launch_bounds__(256) void permute_w_kernel(
    const float* __restrict__ w, float* __restrict__ wp)
{
    extern __shared__ float s[];
    int blk = blockIdx.x;           // 0..191
    int t = threadIdx.x;
#pragma unroll
    for (int rr = 0; rr < 16; ++rr) {
        float4 v = *(const float4*)(w + (size_t)(blk * 16 + rr) * EDIM + t * 4);
        *(float4*)&s[rr * 1028 + t * 4] = v;
    }
    __syncthreads();
#pragma unroll
    for (int it = 0; it < 32; ++it) {
        int o2 = t + it * 256;              // 0..8191
        int nb_l = o2 >> 12;                // 0..1
        int kb   = (o2 >> 5) & 127;
        int lane = o2 & 31;
        int fr = lane >> 2, fc = lane & 3;
        int rl = nb_l * 8 + fr;
        float2 o;
        o.x = roundtf(s[rl * 1028 + kb * 8 + fc]);
        o.y = roundtf(s[rl * 1028 + kb * 8 + fc + 4]);
        *(float2*)(wp + (((size_t)(blk * 2 + nb_l) * 128 + kb) * 32 + lane) * 2) = o;
    }
}

// ---------------------------------------------------------------------------
// Persistent TF32 QKV GEMM (R11 config: BK=32, 4-stage) with L2-resident
// tile order: tile = bid + k*148, bn = tile % 12, bm = tile / 12 ->
// concurrent window = ~13 bm blocks (6.5MB A) + all W (12MB) fits L2.
// 8 warps (2x4), warp tile 64x64, LDSM A-fragments, permuted-W LDS.64 B.
// ---------------------------------------------------------------------------
#define GS_A_BYTES 18432
#define GS_B_BYTES 32768
#define GS_STAGE   (GS_A_BYTES + GS_B_BYTES)   // 51200
#define GS_SMEM    (4 * GS_STAGE)              // 204800

__global__ __launch_bounds__(256, 1) void qkv_gemm_tf32_kernel(
    const float* __restrict__ A, const float* __restrict__ Wp,
    const float* __restrict__ bias, float* __restrict__ C)
{
    extern __shared__ char smem[];
    uint32_t sb = smem_u32(smem);
    int tid  = threadIdx.x;
    int lane = tid & 31;
    int wid  = tid >> 5;          // 0..7
    int wm   = wid >> 2;          // 0..1
    int wn   = wid & 3;           // 0..3
    int bid  = blockIdx.x;        // 0..147

    int nt_local = (NTILES - bid + NSM - 1) / NSM;
    int total_chunks = nt_local * 32;

    auto load_chunk = [&](int q) {
        int tile = bid + (q >> 5) * NSM;
        int c    = q & 31;
        int bn = tile % 12;
        int bm = tile / 12;
        uint32_t base = sb + (q & 3) * GS_STAGE;
        int kbase = c * 32;
#pragma unroll
        for (int i = 0; i < 4; ++i) {      // A: 1024 granules
            int g = tid + i * 256;
            int r = g >> 3, kk = g & 7;
            cp_async16(base + r * 144 + kk * 16,
                       A + (size_t)(bm * 128 + r) * EDIM + kbase + kk * 4);
        }
#pragma unroll
        for (int i = 0; i < 8; ++i) {      // W: 2048 granules (permuted blocks)
            int g = tid + i * 256;
            int nb = g >> 6, kb = (g >> 4) & 3, pr = g & 15;
            cp_async16(base + GS_A_BYTES + g * 16,
                       Wp + ((size_t)(bn * 32 + nb) * 128 + c * 4 + kb) * 64 + pr * 4);
        }
    };

    load_chunk(0); CP_COMMIT();
    load_chunk(1); CP_COMMIT();
    load_chunk(2); CP_COMMIT();

    float acc[4][8][4];
#pragma unroll
    for (int i = 0; i < 4; ++i)
#pragma unroll
        for (int j = 0; j < 8; ++j)
#pragma unroll
            for (int k = 0; k < 4; ++k) acc[i][j][k] = 0.f;

    uint32_t a_off = (uint32_t)((wm * 64 + (lane & 15)) * 144 + (lane >> 4) * 16);
    int qr = lane >> 2;
    int tc = (lane & 3) * 2;

    for (int q = 0; q < total_chunks; ++q) {
        asm volatile("cp.async.wait_group 2;" ::: "memory");
        __syncthreads();
        int s = q & 3;
        uint32_t sA = sb + s * GS_STAGE;
        const char* Bp = smem + s * GS_STAGE + GS_A_BYTES;

#pragma unroll
        for (int ks = 0; ks < 32; ks += 8) {
            int kb = ks >> 3;
            uint32_t fa[4][4];
            uint2 fb[8];
#pragma unroll
            for (int mt = 0; mt < 4; ++mt)
                ldsm4(fa[mt], sA + a_off + mt * (16 * 144) + ks * 4);
#pragma unroll
            for (int nt = 0; nt < 8; ++nt) {
                int nbl = wn * 8 + nt;
                fb[nt] = *(const uint2*)(Bp + (nbl * 4 + kb) * 256 + lane * 8);
            }
#pragma unroll
            for (int mt = 0; mt < 4; ++mt)
#pragma unroll
                for (int nt = 0; nt < 8; ++nt)
                    mma_tf32(acc[mt][nt], fa[mt], fb[nt].x, fb[nt].y);
        }

        if (q + 3 < total_chunks) load_chunk(q + 3);
        CP_COMMIT();

        if ((q & 31) == 31) {
            // ---- epilogue for this tile (loads for next tile in flight) ----
            int tile = bid + (q >> 5) * NSM;
            int bn = tile % 12;
            int bm = tile / 12;
            float scale = (bn < 4) ? 0.125f : 1.0f;   // q * HD^-0.5
#pragma unroll
            for (int mt = 0; mt < 4; ++mt) {
#pragma unroll
                for (int nt = 0; nt < 8; ++nt) {
                    int row = bm * 128 + wm * 64 + mt * 16 + qr;
                    int col = bn * 256 + wn * 64 + nt * 8 + tc;
                    float b0 = bias[col], b1 = bias[col + 1];
                    float2 o0 = make_float2(roundtf((acc[mt][nt][0] + b0) * scale),
                                            roundtf((acc[mt][nt][1] + b1) * scale));
                    float2 o1 = make_float2(roundtf((acc[mt][nt][2] + b0) * scale),
                                            roundtf((acc[mt][nt][3] + b1) * scale));
                    *(float2*)(C + (size_t)row * QKVDIM + col)       = o0;
                    *(float2*)(C + (size_t)(row + 8) * QKVDIM + col) = o1;
#pragma unroll
                    for (int k = 0; k < 4; ++k) acc[mt][nt][k] = 0.f;
                }
            }
        }
    }
}

// ---------------------------------------------------------------------------
// Attention via TF32 mma.sync + LDSM: one block (256 thr) per bh; 3 CTAs/SM.
// SMEM (floats): Qs 128x68 @0, Ks 128x68 @8704, AVG 8x128 @17408 = 72KB.
// V has NO smem tile: AV B-fragments load directly from global (LDG), hidden
// by 24 warps/SM. QK runs in two n-halves to halve live accumulators
// (fits the 85-reg budget of 3 CTAs/SM). S (128x132) overlays Qs+Ks.
// ---------------------------------------------------------------------------
#define AT_K_F   8704
#define AT_AVG_F 17408
#define ATTN_SMEM_BYTES ((AT_AVG_F + 8 * 128) * 4)   // 73728

__global__ void __launch_bounds__(256, 3) attn_kernel(
    const float* __restrict__ qkv, float* __restrict__ attn,
    float* __restrict__ avg_out)
{
    extern __shared__ float sm[];
    float* AVG = sm + AT_AVG_F;
    float* S   = sm;                // overlays Qs+Ks after QK phase
    uint32_t sbase = smem_u32(sm);

    int bh  = blockIdx.x;
    int p   = bh >> 11;
    int rr  = bh & 2047;
    int nid = rr >> 4;
    int h   = rr & 15;
    int t   = threadIdx.x;
    int lane = t & 31;
    int wid  = t >> 5;            // 0..7
    int wm   = wid >> 2;          // 0..1
    int wn   = wid & 3;           // 0..3
    int col = h * HDIM;

    // ---- async gather of Q,K ----
#pragma unroll
    for (int it = 0; it < 8; ++it) {
        int f  = t + it * 256;          // 0..2047
        int i  = f >> 4;                // row 0..127
        int d0 = (f & 15) << 2;         // 0..60
        int rowoff = ((2 * i + p) * 128 + nid) * QKVDIM;
        cp_async16(sbase + (i * 68 + d0) * 4,
                   qkv + rowoff + col + d0);
        cp_async16(sbase + (AT_K_F + i * 68 + d0) * 4,
                   qkv + rowoff + 1024 + col + d0);
    }
    CP_COMMIT();
    asm volatile("cp.async.wait_group 0;" ::: "memory");
    __syncthreads();

    // LDSM per-lane offsets (bytes)
    uint32_t aq_off = (uint32_t)((wm * 64 + (lane & 15)) * 272 + (lane >> 4) * 16);
    uint32_t bk_row0 = (uint32_t)(wn * 32 + (lane & 7) + ((lane & 16) >> 1));
    uint32_t bk_off = AT_K_F * 4 + bk_row0 * 272 + (((lane >> 3) & 1) * 16);

    // ---- scores = Q K^T (TF32), warp tile 64x32 in two 64x16 halves ----
    {
        int qr = lane >> 2, tc = (lane & 3) * 2;
#pragma unroll
        for (int nh = 0; nh < 2; ++nh) {
            float acc[4][2][4];
#pragma unroll
            for (int i = 0; i < 4; ++i)
#pragma unroll
                for (int j = 0; j < 2; ++j)
#pragma unroll
                    for (int k = 0; k < 4; ++k) acc[i][j][k] = 0.f;

#pragma unroll
            for (int ks = 0; ks < 64; ks += 8) {
                uint32_t fa[4][4], fbp[4];
#pragma unroll
                for (int mt = 0; mt < 4; ++mt)
                    ldsm4(fa[mt], sbase + aq_off + mt * (16 * 272) + ks * 4);
                ldsm4(fbp, sbase + bk_off + nh * (16 * 272) + ks * 4);
#pragma unroll
                for (int mt = 0; mt < 4; ++mt) {
#pragma unroll
                    for (int nt = 0; nt < 2; ++nt)
                        mma_tf32(acc[mt][nt], fa[mt], fbp[nt * 2], fbp[nt * 2 + 1]);
                }
            }
            // stash this n-half into registers -> defer store until overlay safe
            // (store to S after __syncthreads below would need acc live; instead
            //  we sync once per nh: all warps finish reading Q/K cols for this
            //  half... Q/K are fully re-read each half, so sync only once after
            //  BOTH halves. Keep acc in a per-half spill to S is unsafe before
            //  sync. Solution: accumulate stores into registers for half 0 is
            //  impossible -> use a block-wide sync between compute and store.)
            __syncthreads();   // all warps done reading Qs/Ks for this half
#pragma unroll
            for (int mt = 0; mt < 4; ++mt) {
#pragma unroll
                for (int nt = 0; nt < 2; ++nt) {
                    int row = wm * 64 + mt * 16 + qr;
                    int cc  = wn * 32 + nh * 16 + nt * 8 + tc;
                    S[row * 132 + cc]           = acc[mt][nt][0];
                    S[row * 132 + cc + 1]       = acc[mt][nt][1];
                    S[(row + 8) * 132 + cc]     = acc[mt][nt][2];
                    S[(row + 8) * 132 + cc + 1] = acc[mt][nt][3];
                }
            }
            __syncthreads();   // stores visible / Q,K region stable per half
        }
    }
    // NOTE: S columns [0,128) overlay Qs+Ks bytes [0,67584) — but K rows for
    // nh=1 live at bytes [34816+...]. The two-sync-per-half pattern above is
    // NOT safe w.r.t. overlay: S writes for half 0 would corrupt K needed by
    // half 1. To keep correctness, S row stride 132 writes for rows 0..127
    // cols 0..31 touch bytes 0..~67000 which includes K region. Therefore we
    // must NOT write S until all K reads complete — enforced here: the loop
    // above syncs BEFORE each store phase, and K for half nh is fully read in
    // that same iteration by every warp (each warp reads only its own wn*32
    // K rows, but S writes span all rows). Half 0 stores would clobber K rows
    // needed by half 1 of OTHER warps? No: every warp reads K rows
    // wn*32+nh*16.. within ITS OWN iteration nh; all warps are at the same nh
    // due to the __syncthreads pair. K rows for nh=1 (rows wn*32+16..31) are
    // NOT read in half 0... but S stores in half 0 write cols wn*32..+15 over
    // rows 0..127 -> byte range includes K rows beyond 16. CONFLICT.
    // => Re-read of K half 1 would be corrupted. Fix: compute BOTH halves
    // before any S store is impossible within 85 regs. Instead: half order
    // swapped for S cols vs K rows decouples nothing. SAFE RESOLUTION:
    // stage half-0 result into the AVG region (1024 floats < 4096 needed)?
    // Insufficient. FINAL: revert to single-pass 64x32 QK (64 acc regs) and
    // accept ptxas reg target; see below.
    // ---- (the code path above is compiled out) ----

    // ---- avg_w + softmax + AV are below; see attn_kernel2 ----
}

// Corrected attention kernel (single-pass QK, acc 64 regs; V from global).
__global__ void __launch_bounds__(256, 3) attn_kernel2(
    const float* __restrict__ qkv, float* __restrict__ attn,
    float* __restrict__ avg_out)
{
    extern __shared__ float sm[];
    float* AVG = sm + AT_AVG_F;
    float* S   = sm;
    uint32_t sbase = smem_u32(sm);

    int bh  = blockIdx.x;
    int p   = bh >> 11;
    int rr  = bh & 2047;
    int nid = rr >> 4;
    int h   = rr & 15;
    int t   = threadIdx.x;
    int lane = t & 31;
    int wid  = t >> 5;
    int wm   = wid >> 2;
    int wn   = wid & 3;
    int col = h * HDIM;

#pragma unroll
    for (int it = 0; it < 8; ++it) {
        int f  = t + it * 256;
        int i  = f >> 4;
        int d0 = (f & 15) << 2;
        int rowoff = ((2 * i + p) * 128 + nid) * QKVDIM;
        cp_async16(sbase + (i * 68 + d0) * 4, qkv + rowoff + col + d0);
        cp_async16(sbase + (AT_K_F + i * 68 + d0) * 4,
                   qkv + rowoff + 1024 + col + d0);
    }
    CP_COMMIT();
    asm volatile("cp.async.wait_group 0;" ::: "memory");
    __syncthreads();

    uint32_t aq_off = (uint32_t)((wm * 64 + (lane & 15)) * 272 + (lane >> 4) * 16);
    uint32_t bk_row = (uint32_t)(wn * 32 + (lane & 7) + ((lane & 16) >> 1));
    uint32_t bk_off = AT_K_F * 4 + bk_row * 272 + (((lane >> 3) & 1) * 16);

    float acc[4][4][4];
#pragma unroll
    for (int i = 0; i < 4; ++i)
#pragma unroll
        for (int j = 0; j < 4; ++j)
#pragma unroll
            for (int k = 0; k < 4; ++k) acc[i][j][k] = 0.f;

#pragma unroll
    for (int ks = 0; ks < 64; ks += 8) {
        uint32_t fa[4][4], fbp[2][4];
#pragma unroll
        for (int mt = 0; mt < 4; ++mt)
            ldsm4(fa[mt], sbase + aq_off + mt * (16 * 272) + ks * 4);
#pragma unroll
        for (int ntp = 0; ntp < 2; ++ntp)
            ldsm4(fbp[ntp], sbase + bk_off + ntp * (16 * 272) + ks * 4);
#pragma unroll
        for (int mt = 0; mt < 4; ++mt)
#pragma unroll
            for (int nt = 0; nt < 4; ++nt) {
                int np = nt >> 1, hh = (nt & 1) * 2;
                mma_tf32(acc[mt][nt], fa[mt], fbp[np][hh], fbp[np][hh + 1]);
            }
    }
    __syncthreads();

    {
        int qr = lane >> 2, tc = (lane & 3) * 2;
#pragma unroll
        for (int mt = 0; mt < 4; ++mt)
#pragma unroll
            for (int nt = 0; nt < 4; ++nt) {
                int row = wm * 64 + mt * 16 + qr;
                int cc  = wn * 32 + nt * 8 + tc;
                S[row * 132 + cc]           = acc[mt][nt][0];
                S[row * 132 + cc + 1]       = acc[mt][nt][1];
                S[(row + 8) * 132 + cc]     = acc[mt][nt][2];
                S[(row + 8) * 132 + cc + 1] = acc[mt][nt][3];
            }
    }
    __syncthreads();

    // softmax (16 rows/warp) + fused avg partials
    {
        float cs0 = 0.f, cs1 = 0.f, cs2 = 0.f, cs3 = 0.f;
#pragma unroll
        for (int r8 = 0; r8 < 16; ++r8) {
            int row = wid * 16 + r8;
            float4 v = *(float4*)&S[row * 132 + lane * 4];
            float mx = fmaxf(fmaxf(v.x, v.y), fmaxf(v.z, v.w));
#pragma unroll
            for (int o = 16; o > 0; o >>= 1)
                mx = fmaxf(mx, __shfl_xor_sync(0xffffffffu, mx, o));
            v.x = __expf(v.x - mx); v.y = __expf(v.y - mx);
            v.z = __expf(v.z - mx); v.w = __expf(v.w - mx);
            float sum = v.x + v.y + v.z + v.w;
#pragma unroll
            for (int o = 16; o > 0; o >>= 1)
                sum += __shfl_xor_sync(0xffffffffu, sum, o);
            float inv = 1.0f / sum;
            v.x = roundtf(v.x * inv); v.y = roundtf(v.y * inv);
            v.z = roundtf(v.z * inv); v.w = roundtf(v.w * inv);
            cs0 += v.x; cs1 += v.y; cs2 += v.z; cs3 += v.w;
            *(float4*)&S[row * 132 + lane * 4] = v;
        }
        *(float4*)&AVG[wid * 128 + lane * 4] = make_float4(cs0, cs1, cs2, cs3);
    }
    __syncthreads();

    if (t < 128) {
        float s = 0.f;
#pragma unroll
        for (int w = 0; w < 8; ++w) s += AVG[w * 128 + t];
        avg_out[bh * 128 + t] = s * 0.0625f;
    }

    // ---- A·V: A = S via LDSM; V fragments DIRECT FROM GLOBAL ----
    float av[4][2][4];
    {
        int fr = lane >> 2;
        int fc = lane & 3;
        const float* vb = qkv + (size_t)(p * 128 + nid) * QKVDIM + 2048 + col;
        int nb0 = wn * 16 + fr;
        uint32_t as_off = (uint32_t)((wm * 64 + (lane & 15)) * 528 + (lane >> 4) * 16);
#pragma unroll
        for (int i = 0; i < 4; ++i)
#pragma unroll
            for (int j = 0; j < 2; ++j)
#pragma unroll
                for (int k = 0; k < 4; ++k) av[i][j][k] = 0.f;

#pragma unroll
        for (int ks = 0; ks < 128; ks += 8) {
            uint32_t fa[4][4];
            uint32_t fb00, fb01, fb10, fb11;
            size_t r0 = (size_t)(ks + fc) * (2 * QKVDIM * 128 / 256) * 256;
            // i stride in floats: 2*128*QKVDIM per i? row=(2i+p)*128+nid ->
            // delta per i = 2*128*QKVDIM = 786432 floats
            const float* v0 = vb + (size_t)(ks + fc) * 786432;
            const float* v1 = vb + (size_t)(ks + fc + 4) * 786432;
            fb00 = __float_as_uint(v0[nb0]);
            fb01 = __float_as_uint(v1[nb0]);
            fb10 = __float_as_uint(v0[nb0 + 8]);
            fb11 = __float_as_uint(v1[nb0 + 8]);
#pragma unroll
            for (int mt = 0; mt < 4; ++mt)
                ldsm4(fa[mt], sbase + as_off + mt * (16 * 528) + ks * 4);
#pragma unroll
            for (int mt = 0; mt < 4; ++mt) {
                mma_tf32(av[mt][0], fa[mt], fb00, fb01);
                mma_tf32(av[mt][1], fa[mt], fb10, fb11);
            }
        }
    }
    __syncthreads();

    {
        int qr = lane >> 2, tc = (lane & 3) * 2;
#pragma unroll
        for (int mt = 0; mt < 4; ++mt)
#pragma unroll
            for (int nt = 0; nt < 2; ++nt) {
                int row = wm * 64 + mt * 16 + qr;
                int cc  = wn * 16 + nt * 8 + tc;
                *(float2*)&S[row * 68 + cc] =
                    make_float2(av[mt][nt][0], av[mt][nt][1]);
                *(float2*)&S[(row + 8) * 68 + cc] =
                    make_float2(av[mt][nt][2], av[mt][nt][3]);
            }
    }
    __syncthreads();
#pragma unroll
    for (int it = 0; it < 8; ++it) {
        int f  = t + it * 256;
        int row = f >> 4;
        int c4  = (f & 15) << 2;
        float4 v = *(float4*)&S[row * 68 + c4];
        int orow = (2 * row + p) * 128 + nid;
        *(float4*)&attn[(size_t)orow * EDIM + col + c4] = v;
    }
}

// ---------------------------------------------------------------------------
// Launch
// ---------------------------------------------------------------------------
extern "C" void kernel_launch(void* const* d_in, const int* in_sizes, int n_in,
                              void* d_out, int out_size)
{
    const float* x    = (const float*)d_in[0];
    const float* ln1w = (const float*)d_in[1];
    const float* ln1b = (const float*)d_in[2];
    const float* inw  = (const float*)d_in[3];
    const float* inb  = (const float*)d_in[4];
    const float* ln2w = (const float*)d_in[5];
    const float* ln2b = (const float*)d_in[6];
    float* out = (float*)d_out;

    float *xn, *qkv, *attn, *wtf;
    cudaGetSymbolAddress((void**)&xn,   g_xn);
    cudaGetSymbolAddress((void**)&qkv,  g_qkv);
    cudaGetSymbolAddress((void**)&attn, g_attn);
    cudaGetSymbolAddress((void**)&wtf,  g_wtf);

    cudaFuncSetAttribute(attn_kernel2,
                         cudaFuncAttributeMaxDynamicSharedMemorySize,
                         ATTN_SMEM_BYTES);
    cudaFuncSetAttribute(qkv_gemm_tf32_kernel,
                         cudaFuncAttributeMaxDynamicSharedMemorySize,
                         GS_SMEM);
    cudaFuncSetAttribute(permute_w_kernel,
                         cudaFuncAttributeMaxDynamicSharedMemorySize,
                         PW_SMEM);

    // 1) xn = LN1(x), tf32-rounded (also the residual for LN2)
    ln_kernel<<<NROWS, 256>>>(x, nullptr, ln1w, ln1b, xn, 1);
    // 2) permute + round weights into B-fragment layout
    permute_w_kernel<<<192, 256, PW_SMEM>>>(inw, wtf);
    // 3) persistent TF32 QKV GEMM (R11 pipeline + L2-resident tile order)
    qkv_gemm_tf32_kernel<<<NSM, 256, GS_SMEM>>>(xn, wtf, inb, qkv);
    // 4) TF32 attention + avg_w (3 CTAs/SM, V direct from global)
    attn_kernel2<<<NBH, 256, ATTN_SMEM_BYTES>>>(qkv, attn, out + OUT_ELEMS);
    // 5) out = LN2(xn + attn)
    ln_kernel<<<NROWS, 256>>>(xn, attn, ln2w, ln2b, out, 0);
}

// round 14
// speedup vs baseline: 1.0300x; 1.0288x over previous
#include <cuda_runtime.h>
#include <cstdint>

// ---------------------------------------------------------------------------
// Problem constants
// ---------------------------------------------------------------------------
#define EDIM   1024
#define NAQ    128
#define BSZ    256
#define NROWS  (BSZ * NAQ)          // 32768
#define QKVDIM 3072
#define HEADS  16
#define HDIM   64
#define NBH    (BSZ * HEADS)        // 4096 attention batches
#define OUT_ELEMS (NROWS * EDIM)
#define NTILES 3072                 // 256 bm x 12 bn
#define NSM    148

// ---------------------------------------------------------------------------
// Scratch (device globals: allocation-free)
// ---------------------------------------------------------------------------
__device__ float g_xn  [(size_t)NROWS * EDIM];       // ln1(x), tf32-rounded
__device__ float g_qkv [(size_t)NROWS * QKVDIM];     // qkv (q scaled), tf32-rounded
__device__ float g_attn[(size_t)NROWS * EDIM];       // attention output
__device__ float g_wtf [(size_t)QKVDIM * EDIM];      // in_w, fragment-permuted tf32

// ---------------------------------------------------------------------------
// Helpers (portable subset: harness lowers through compute_103)
// ---------------------------------------------------------------------------
__device__ __forceinline__ uint32_t smem_u32(const void* p) {
    uint32_t a;
    asm("{ .reg .u64 t; cvta.to.shared.u64 t, %1; cvt.u32.u64 %0, t; }"
        : "=r"(a) : "l"(p));
    return a;
}
__device__ __forceinline__ void cp_async16(uint32_t dst, const void* src) {
    asm volatile("cp.async.cg.shared.global [%0], [%1], 16;"
                 :: "r"(dst), "l"(src) : "memory");
}
#define CP_COMMIT() asm volatile("cp.async.commit_group;" ::: "memory")

__device__ __forceinline__ uint32_t f2tf(float f) {
    uint32_t r;
    asm("cvt.rna.tf32.f32 %0, %1;" : "=r"(r) : "f"(f));
    return r;
}
__device__ __forceinline__ float roundtf(float f) {
    return __uint_as_float(f2tf(f));
}
__device__ __forceinline__ void mma_tf32(float* c, const uint32_t* a,
                                         uint32_t b0, uint32_t b1) {
    asm volatile(
        "mma.sync.aligned.m16n8k8.row.col.f32.tf32.tf32.f32 "
        "{%0,%1,%2,%3}, {%4,%5,%6,%7}, {%8,%9}, {%0,%1,%2,%3};"
        : "+f"(c[0]), "+f"(c[1]), "+f"(c[2]), "+f"(c[3])
        : "r"(a[0]), "r"(a[1]), "r"(a[2]), "r"(a[3]), "r"(b0), "r"(b1));
}
__device__ __forceinline__ void ldsm4(uint32_t* r, uint32_t addr) {
    asm volatile("ldmatrix.sync.aligned.m8n8.x4.shared.b16 {%0,%1,%2,%3}, [%4];"
                 : "=r"(r[0]), "=r"(r[1]), "=r"(r[2]), "=r"(r[3]) : "r"(addr));
}

// ---------------------------------------------------------------------------
// LayerNorm (+ optional residual, optional tf32 rounding of output)
// ---------------------------------------------------------------------------
__global__ __launch_bounds__(256) void ln_kernel(
    const float* __restrict__ in, const float* __restrict__ res,
    const float* __restrict__ w, const float* __restrict__ b,
    float* __restrict__ out, int rnd)
{
    __shared__ float red_s[8];
    __shared__ float red_q[8];
    size_t row = blockIdx.x;
    int t = threadIdx.x;

    const float4* px = (const float4*)(in + row * EDIM);
    float4 v = px[t];
    if (res != nullptr) {
        const float4* pr = (const float4*)(res + row * EDIM);
        float4 rv = pr[t];
        v.x += rv.x; v.y += rv.y; v.z += rv.z; v.w += rv.w;
    }
    float s = v.x + v.y + v.z + v.w;
    float q = v.x * v.x + v.y * v.y + v.z * v.z + v.w * v.w;
#pragma unroll
    for (int o = 16; o > 0; o >>= 1) {
        s += __shfl_xor_sync(0xffffffffu, s, o);
        q += __shfl_xor_sync(0xffffffffu, q, o);
    }
    if ((t & 31) == 0) { red_s[t >> 5] = s; red_q[t >> 5] = q; }
    __syncthreads();
    float tot = 0.f, totq = 0.f;
#pragma unroll
    for (int k = 0; k < 8; ++k) { tot += red_s[k]; totq += red_q[k]; }

    float mean = tot * (1.0f / EDIM);
    float var  = totq * (1.0f / EDIM) - mean * mean;
    float rstd = rsqrtf(var + 1e-5f);

    int c0 = t * 4;
    float4 wv = *(const float4*)(w + c0);
    float4 bv = *(const float4*)(b + c0);
    float4 o4;
    o4.x = (v.x - mean) * rstd * wv.x + bv.x;
    o4.y = (v.y - mean) * rstd * wv.y + bv.y;
    o4.z = (v.z - mean) * rstd * wv.z + bv.z;
    o4.w = (v.w - mean) * rstd * wv.w + bv.w;
    if (rnd) {
        o4.x = roundtf(o4.x); o4.y = roundtf(o4.y);
        o4.z = roundtf(o4.z); o4.w = roundtf(o4.w);
    }
    ((float4*)(out + row * EDIM))[t] = o4;
}

// ---------------------------------------------------------------------------
// Weight permute: in_w (3072x1024 row-major fp32) -> B-fragment order, tf32.
// Output: [nb 0..383][kb 0..127][lane 0..31][2]
//   val = { W[8nb+fr][8kb+fc], W[8nb+fr][8kb+fc+4] },  fr=lane>>2, fc=lane&3
// ---------------------------------------------------------------------------
#define PW_SMEM (16 * 1028 * 4)     // 65792 bytes

__global__ __launch_bounds__(256) void permute_w_kernel(
    const float* __restrict__ w, float* __restrict__ wp)
{
    extern __shared__ float s[];
    int blk = blockIdx.x;           // 0..191
    int t = threadIdx.x;
#pragma unroll
    for (int rr = 0; rr < 16; ++rr) {
        float4 v = *(const float4*)(w + (size_t)(blk * 16 + rr) * EDIM + t * 4);
        *(float4*)&s[rr * 1028 + t * 4] = v;
    }
    __syncthreads();
#pragma unroll
    for (int it = 0; it < 32; ++it) {
        int o2 = t + it * 256;              // 0..8191
        int nb_l = o2 >> 12;                // 0..1
        int kb   = (o2 >> 5) & 127;
        int lane = o2 & 31;
        int fr = lane >> 2, fc = lane & 3;
        int rl = nb_l * 8 + fr;
        float2 o;
        o.x = roundtf(s[rl * 1028 + kb * 8 + fc]);
        o.y = roundtf(s[rl * 1028 + kb * 8 + fc + 4]);
        *(float2*)(wp + (((size_t)(blk * 2 + nb_l) * 128 + kb) * 32 + lane) * 2) = o;
    }
}

// ---------------------------------------------------------------------------
// Persistent TF32 QKV GEMM (R11 pipeline: BK=32, 4-stage) with L2-resident
// tile order: tile = bid + k*148, bn = tile % 12, bm = tile / 12 ->
// concurrent window = ~13 bm blocks (6.5MB A) + all W (12MB) fits L2.
// 8 warps (2x4), warp tile 64x64, LDSM A-fragments, permuted-W LDS.64 B.
// ---------------------------------------------------------------------------
#define GS_A_BYTES 18432
#define GS_B_BYTES 32768
#define GS_STAGE   (GS_A_BYTES + GS_B_BYTES)   // 51200
#define GS_SMEM    (4 * GS_STAGE)              // 204800

__global__ __launch_bounds__(256, 1) void qkv_gemm_tf32_kernel(
    const float* __restrict__ A, const float* __restrict__ Wp,
    const float* __restrict__ bias, float* __restrict__ C)
{
    extern __shared__ char smem[];
    uint32_t sb = smem_u32(smem);
    int tid  = threadIdx.x;
    int lane = tid & 31;
    int wid  = tid >> 5;          // 0..7
    int wm   = wid >> 2;          // 0..1
    int wn   = wid & 3;           // 0..3
    int bid  = blockIdx.x;        // 0..147

    int nt_local = (NTILES - bid + NSM - 1) / NSM;
    int total_chunks = nt_local * 32;

    auto load_chunk = [&](int q) {
        int tile = bid + (q >> 5) * NSM;
        int c    = q & 31;
        int bn = tile % 12;
        int bm = tile / 12;
        uint32_t base = sb + (q & 3) * GS_STAGE;
        int kbase = c * 32;
#pragma unroll
        for (int i = 0; i < 4; ++i) {      // A: 1024 granules
            int g = tid + i * 256;
            int r = g >> 3, kk = g & 7;
            cp_async16(base + r * 144 + kk * 16,
                       A + (size_t)(bm * 128 + r) * EDIM + kbase + kk * 4);
        }
#pragma unroll
        for (int i = 0; i < 8; ++i) {      // W: 2048 granules (permuted blocks)
            int g = tid + i * 256;
            int nb = g >> 6, kb = (g >> 4) & 3, pr = g & 15;
            cp_async16(base + GS_A_BYTES + g * 16,
                       Wp + ((size_t)(bn * 32 + nb) * 128 + c * 4 + kb) * 64 + pr * 4);
        }
    };

    load_chunk(0); CP_COMMIT();
    load_chunk(1); CP_COMMIT();
    load_chunk(2); CP_COMMIT();

    float acc[4][8][4];
#pragma unroll
    for (int i = 0; i < 4; ++i)
#pragma unroll
        for (int j = 0; j < 8; ++j)
#pragma unroll
            for (int k = 0; k < 4; ++k) acc[i][j][k] = 0.f;

    uint32_t a_off = (uint32_t)((wm * 64 + (lane & 15)) * 144 + (lane >> 4) * 16);
    int qr = lane >> 2;
    int tc = (lane & 3) * 2;

    for (int q = 0; q < total_chunks; ++q) {
        asm volatile("cp.async.wait_group 2;" ::: "memory");
        __syncthreads();
        int s = q & 3;
        uint32_t sA = sb + s * GS_STAGE;
        const char* Bp = smem + s * GS_STAGE + GS_A_BYTES;

#pragma unroll
        for (int ks = 0; ks < 32; ks += 8) {
            int kb = ks >> 3;
            uint32_t fa[4][4];
            uint2 fb[8];
#pragma unroll
            for (int mt = 0; mt < 4; ++mt)
                ldsm4(fa[mt], sA + a_off + mt * (16 * 144) + ks * 4);
#pragma unroll
            for (int nt = 0; nt < 8; ++nt) {
                int nbl = wn * 8 + nt;
                fb[nt] = *(const uint2*)(Bp + (nbl * 4 + kb) * 256 + lane * 8);
            }
#pragma unroll
            for (int mt = 0; mt < 4; ++mt)
#pragma unroll
                for (int nt = 0; nt < 8; ++nt)
                    mma_tf32(acc[mt][nt], fa[mt], fb[nt].x, fb[nt].y);
        }

        if (q + 3 < total_chunks) load_chunk(q + 3);
        CP_COMMIT();

        if ((q & 31) == 31) {
            // ---- epilogue for this tile (loads for next tile in flight) ----
            int tile = bid + (q >> 5) * NSM;
            int bn = tile % 12;
            int bm = tile / 12;
            float scale = (bn < 4) ? 0.125f : 1.0f;   // q * HD^-0.5
#pragma unroll
            for (int mt = 0; mt < 4; ++mt) {
#pragma unroll
                for (int nt = 0; nt < 8; ++nt) {
                    int row = bm * 128 + wm * 64 + mt * 16 + qr;
                    int col = bn * 256 + wn * 64 + nt * 8 + tc;
                    float b0 = bias[col], b1 = bias[col + 1];
                    float2 o0 = make_float2(roundtf((acc[mt][nt][0] + b0) * scale),
                                            roundtf((acc[mt][nt][1] + b1) * scale));
                    float2 o1 = make_float2(roundtf((acc[mt][nt][2] + b0) * scale),
                                            roundtf((acc[mt][nt][3] + b1) * scale));
                    *(float2*)(C + (size_t)row * QKVDIM + col)       = o0;
                    *(float2*)(C + (size_t)(row + 8) * QKVDIM + col) = o1;
#pragma unroll
                    for (int k = 0; k < 4; ++k) acc[mt][nt][k] = 0.f;
                }
            }
        }
    }
}

// ---------------------------------------------------------------------------
// Attention via TF32 mma.sync + LDSM (R12 winner): one block per bh;
// 2 CTAs/SM. SMEM (floats): Qs 128x68 @0, Ks 128x68 @8704, Vs 128x72 @17408,
// AVG 8x128 @26624. S (128x132) overlays Qs+Ks after QK^T.
// avg_w fused into softmax; V cp.async group overlaps QK + softmax.
// ---------------------------------------------------------------------------
#define AT_K_F   8704
#define AT_V_F   17408
#define AT_AVG_F 26624
#define ATTN_SMEM_BYTES ((AT_AVG_F + 8 * 128) * 4)   // 110592

__global__ void __launch_bounds__(256, 2) attn_kernel(
    const float* __restrict__ qkv, float* __restrict__ attn,
    float* __restrict__ avg_out)
{
    extern __shared__ float sm[];
    float* Vs  = sm + AT_V_F;
    float* AVG = sm + AT_AVG_F;
    float* S   = sm;                // overlays Qs+Ks after QK phase
    uint32_t sbase = smem_u32(sm);

    int bh  = blockIdx.x;
    int p   = bh >> 11;
    int rr  = bh & 2047;
    int nid = rr >> 4;
    int h   = rr & 15;
    int t   = threadIdx.x;
    int lane = t & 31;
    int wid  = t >> 5;            // 0..7
    int wm   = wid >> 2;          // 0..1
    int wn   = wid & 3;           // 0..3
    int col = h * HDIM;

    // ---- async gather of Q,K (group 1) and V (group 0, overlapped) ----
#pragma unroll
    for (int it = 0; it < 8; ++it) {
        int f  = t + it * 256;          // 0..2047
        int i  = f >> 4;                // row 0..127
        int d0 = (f & 15) << 2;         // 0..60
        int rowoff = ((2 * i + p) * 128 + nid) * QKVDIM;
        cp_async16(sbase + (i * 68 + d0) * 4,
                   qkv + rowoff + col + d0);
        cp_async16(sbase + (AT_K_F + i * 68 + d0) * 4,
                   qkv + rowoff + 1024 + col + d0);
    }
    CP_COMMIT();
#pragma unroll
    for (int it = 0; it < 8; ++it) {
        int f  = t + it * 256;
        int i  = f >> 4;
        int d0 = (f & 15) << 2;
        int rowoff = ((2 * i + p) * 128 + nid) * QKVDIM;
        cp_async16(sbase + (AT_V_F + i * 72 + d0) * 4,
                   qkv + rowoff + 2048 + col + d0);
    }
    CP_COMMIT();
    asm volatile("cp.async.wait_group 1;" ::: "memory");  // Q,K ready
    __syncthreads();

    // LDSM per-lane offsets (bytes)
    uint32_t aq_off = (uint32_t)((wm * 64 + (lane & 15)) * 272 + (lane >> 4) * 16);
    uint32_t bk_row = (uint32_t)(wn * 32 + (lane & 7) + ((lane & 16) >> 1));
    uint32_t bk_off = AT_K_F * 4 + bk_row * 272 + (((lane >> 3) & 1) * 16);

    // ---- scores = Q K^T (TF32), warp tile 64x32, K=64; kept in registers ----
    float acc[4][4][4];
#pragma unroll
    for (int i = 0; i < 4; ++i)
#pragma unroll
        for (int j = 0; j < 4; ++j)
#pragma unroll
            for (int k = 0; k < 4; ++k) acc[i][j][k] = 0.f;

#pragma unroll
    for (int ks = 0; ks < 64; ks += 8) {
        uint32_t fa[4][4], fbp[2][4];
#pragma unroll
        for (int mt = 0; mt < 4; ++mt)
            ldsm4(fa[mt], sbase + aq_off + mt * (16 * 272) + ks * 4);
#pragma unroll
        for (int ntp = 0; ntp < 2; ++ntp)
            ldsm4(fbp[ntp], sbase + bk_off + ntp * (16 * 272) + ks * 4);
#pragma unroll
        for (int mt = 0; mt < 4; ++mt) {
#pragma unroll
            for (int nt = 0; nt < 4; ++nt) {
                int np = nt >> 1, hh = (nt & 1) * 2;
                mma_tf32(acc[mt][nt], fa[mt], fbp[np][hh], fbp[np][hh + 1]);
            }
        }
    }
    __syncthreads();   // all warps done reading Qs/Ks before S overlays them

    {
        int qr = lane >> 2, tc = (lane & 3) * 2;
#pragma unroll
        for (int mt = 0; mt < 4; ++mt) {
#pragma unroll
            for (int nt = 0; nt < 4; ++nt) {
                int row = wm * 64 + mt * 16 + qr;
                int cc  = wn * 32 + nt * 8 + tc;
                S[row * 132 + cc]           = acc[mt][nt][0];
                S[row * 132 + cc + 1]       = acc[mt][nt][1];
                S[(row + 8) * 132 + cc]     = acc[mt][nt][2];
                S[(row + 8) * 132 + cc + 1] = acc[mt][nt][3];
            }
        }
    }
    __syncthreads();

    // ---- softmax (16 rows/warp, lane-parallel) + fused avg_w partials ----
    {
        float cs0 = 0.f, cs1 = 0.f, cs2 = 0.f, cs3 = 0.f;
#pragma unroll
        for (int r8 = 0; r8 < 16; ++r8) {
            int row = wid * 16 + r8;
            float4 v = *(float4*)&S[row * 132 + lane * 4];
            float mx = fmaxf(fmaxf(v.x, v.y), fmaxf(v.z, v.w));
#pragma unroll
            for (int o = 16; o > 0; o >>= 1)
                mx = fmaxf(mx, __shfl_xor_sync(0xffffffffu, mx, o));
            v.x = __expf(v.x - mx); v.y = __expf(v.y - mx);
            v.z = __expf(v.z - mx); v.w = __expf(v.w - mx);
            float sum = v.x + v.y + v.z + v.w;
#pragma unroll
            for (int o = 16; o > 0; o >>= 1)
                sum += __shfl_xor_sync(0xffffffffu, sum, o);
            float inv = 1.0f / sum;
            v.x = roundtf(v.x * inv); v.y = roundtf(v.y * inv);
            v.z = roundtf(v.z * inv); v.w = roundtf(v.w * inv);
            cs0 += v.x; cs1 += v.y; cs2 += v.z; cs3 += v.w;
            *(float4*)&S[row * 132 + lane * 4] = v;
        }
        *(float4*)&AVG[wid * 128 + lane * 4] = make_float4(cs0, cs1, cs2, cs3);
    }
    asm volatile("cp.async.wait_group 0;" ::: "memory");  // V ready
    __syncthreads();

    // ---- avg_w final reduce across 8 warps ----
    if (t < 128) {
        float s = 0.f;
#pragma unroll
        for (int w = 0; w < 8; ++w) s += AVG[w * 128 + t];
        avg_out[bh * 128 + t] = s * 0.0625f;
    }

    // ---- A·V (TF32): A = S via LDSM, warp tile 64x16, K=128 ----
    float av[4][2][4];
    {
        int fr = lane >> 2;
        int fc = lane & 3;
        uint32_t as_off = (uint32_t)((wm * 64 + (lane & 15)) * 528 + (lane >> 4) * 16);
#pragma unroll
        for (int i = 0; i < 4; ++i)
#pragma unroll
            for (int j = 0; j < 2; ++j)
#pragma unroll
                for (int k = 0; k < 4; ++k) av[i][j][k] = 0.f;

#pragma unroll
        for (int ks = 0; ks < 128; ks += 8) {
            uint32_t fa[4][4], fb[2][2];
#pragma unroll
            for (int mt = 0; mt < 4; ++mt)
                ldsm4(fa[mt], sbase + as_off + mt * (16 * 528) + ks * 4);
#pragma unroll
            for (int nt = 0; nt < 2; ++nt) {
                int nb = wn * 16 + nt * 8 + fr;
                fb[nt][0] = __float_as_uint(Vs[(ks + fc) * 72 + nb]);
                fb[nt][1] = __float_as_uint(Vs[(ks + fc + 4) * 72 + nb]);
            }
#pragma unroll
            for (int mt = 0; mt < 4; ++mt)
#pragma unroll
                for (int nt = 0; nt < 2; ++nt)
                    mma_tf32(av[mt][nt], fa[mt], fb[nt][0], fb[nt][1]);
        }
    }
    __syncthreads();   // everyone done reading S before OUT overlays it

    // ---- stage output in smem (stride 68), then coalesced global stores ----
    {
        int qr = lane >> 2, tc = (lane & 3) * 2;
#pragma unroll
        for (int mt = 0; mt < 4; ++mt) {
#pragma unroll
            for (int nt = 0; nt < 2; ++nt) {
                int row = wm * 64 + mt * 16 + qr;
                int cc  = wn * 16 + nt * 8 + tc;
                *(float2*)&S[row * 68 + cc] =
                    make_float2(av[mt][nt][0], av[mt][nt][1]);
                *(float2*)&S[(row + 8) * 68 + cc] =
                    make_float2(av[mt][nt][2], av[mt][nt][3]);
            }
        }
    }
    __syncthreads();
#pragma unroll
    for (int it = 0; it < 8; ++it) {
        int f  = t + it * 256;
        int row = f >> 4;
        int c4  = (f & 15) << 2;
        float4 v = *(float4*)&S[row * 68 + c4];
        int orow = (2 * row + p) * 128 + nid;
        *(float4*)&attn[(size_t)orow * EDIM + col + c4] = v;
    }
}

// ---------------------------------------------------------------------------
// Launch
// ---------------------------------------------------------------------------
extern "C" void kernel_launch(void* const* d_in, const int* in_sizes, int n_in,
                              void* d_out, int out_size)
{
    const float* x    = (const float*)d_in[0];
    const float* ln1w = (const float*)d_in[1];
    const float* ln1b = (const float*)d_in[2];
    const float* inw  = (const float*)d_in[3];
    const float* inb  = (const float*)d_in[4];
    const float* ln2w = (const float*)d_in[5];
    const float* ln2b = (const float*)d_in[6];
    float* out = (float*)d_out;

    float *xn, *qkv, *attn, *wtf;
    cudaGetSymbolAddress((void**)&xn,   g_xn);
    cudaGetSymbolAddress((void**)&qkv,  g_qkv);
    cudaGetSymbolAddress((void**)&attn, g_attn);
    cudaGetSymbolAddress((void**)&wtf,  g_wtf);

    cudaFuncSetAttribute(attn_kernel,
                         cudaFuncAttributeMaxDynamicSharedMemorySize,
                         ATTN_SMEM_BYTES);
    cudaFuncSetAttribute(qkv_gemm_tf32_kernel,
                         cudaFuncAttributeMaxDynamicSharedMemorySize,
                         GS_SMEM);
    cudaFuncSetAttribute(permute_w_kernel,
                         cudaFuncAttributeMaxDynamicSharedMemorySize,
                         PW_SMEM);

    // 1) xn = LN1(x), tf32-rounded (also the residual for LN2)
    ln_kernel<<<NROWS, 256>>>(x, nullptr, ln1w, ln1b, xn, 1);
    // 2) permute + round weights into B-fragment layout
    permute_w_kernel<<<192, 256, PW_SMEM>>>(inw, wtf);
    // 3) persistent TF32 QKV GEMM (R11 pipeline + L2-resident tile order)
    qkv_gemm_tf32_kernel<<<NSM, 256, GS_SMEM>>>(xn, wtf, inb, qkv);
    // 4) TF32 attention + avg_w (R12 winner: 2 CTAs/SM, V smem, fused avg)
    attn_kernel<<<NBH, 256, ATTN_SMEM_BYTES>>>(qkv, attn, out + OUT_ELEMS);
    // 5) out = LN2(xn + attn)
    ln_kernel<<<NROWS, 256>>>(xn, attn, ln2w, ln2b, out, 0);
}